// round 1
// baseline (speedup 1.0000x reference)
#include <cuda_runtime.h>
#include <math.h>

#define SEQ_LEN 16384
#define D       1024
#define CSZ     128
#define NCH     128

// ---------------- scratch (static device globals; no runtime allocs) --------
__device__ float g_K[(size_t)SEQ_LEN * D];
__device__ float g_V[(size_t)SEQ_LEN * D];
__device__ float g_Q[(size_t)SEQ_LEN * D];
__device__ float g_M[D * D];
__device__ float g_S[D * D];
__device__ float g_err[CSZ * D];
__device__ float g_alpha[NCH];

__device__ __forceinline__ float silu_f(float x) { return x / (1.0f + __expf(-x)); }

// ---------------- zero init for M, S ----------------------------------------
__global__ __launch_bounds__(256) void zero_kernel(float* __restrict__ M, float* __restrict__ S)
{
    int idx = blockIdx.x * 256 + threadIdx.x;      // 1024*256 threads, one float4 each
    float4 z = make_float4(0.f, 0.f, 0.f, 0.f);
    ((float4*)M)[idx] = z;
    ((float4*)S)[idx] = z;
}

// ---------------- projection GEMM: C = silu(A @ B^T) ------------------------
// A [16384,1024] row-major, B (weights) [1024,1024] row-major ([n,k]).
// 128x128x16 tile, 256 threads, 8x8 micro-tile.
__global__ __launch_bounds__(256) void proj_kernel(
    const float* __restrict__ A, const float* __restrict__ B, float* __restrict__ C)
{
    __shared__ float As[16][132];
    __shared__ float Bs[16][132];
    const int t  = threadIdx.x;
    const int tx = t & 15, ty = t >> 4;
    const int lr = t >> 2;             // 0..63
    const int lk = (t & 3) * 4;        // 0,4,8,12
    const float* Ab = A + (size_t)blockIdx.y * 128 * D;
    const float* Bb = B + (size_t)blockIdx.x * 128 * D;

    float acc[8][8];
    #pragma unroll
    for (int i = 0; i < 8; i++)
        #pragma unroll
        for (int j = 0; j < 8; j++) acc[i][j] = 0.f;

    for (int k0 = 0; k0 < D; k0 += 16) {
        #pragma unroll
        for (int h = 0; h < 2; h++) {
            float4 va = *(const float4*)(Ab + (size_t)(lr + h * 64) * D + k0 + lk);
            As[lk + 0][lr + h * 64] = va.x; As[lk + 1][lr + h * 64] = va.y;
            As[lk + 2][lr + h * 64] = va.z; As[lk + 3][lr + h * 64] = va.w;
            float4 vb = *(const float4*)(Bb + (size_t)(lr + h * 64) * D + k0 + lk);
            Bs[lk + 0][lr + h * 64] = vb.x; Bs[lk + 1][lr + h * 64] = vb.y;
            Bs[lk + 2][lr + h * 64] = vb.z; Bs[lk + 3][lr + h * 64] = vb.w;
        }
        __syncthreads();
        #pragma unroll
        for (int kk = 0; kk < 16; kk++) {
            float a[8], b[8];
            *(float4*)&a[0] = *(float4*)&As[kk][ty * 4];
            *(float4*)&a[4] = *(float4*)&As[kk][64 + ty * 4];
            *(float4*)&b[0] = *(float4*)&Bs[kk][tx * 4];
            *(float4*)&b[4] = *(float4*)&Bs[kk][64 + tx * 4];
            #pragma unroll
            for (int i = 0; i < 8; i++)
                #pragma unroll
                for (int j = 0; j < 8; j++)
                    acc[i][j] = fmaf(a[i], b[j], acc[i][j]);
        }
        __syncthreads();
    }
    const int rb = blockIdx.y * 128, cb = blockIdx.x * 128;
    #pragma unroll
    for (int i = 0; i < 8; i++) {
        int r = rb + ((i < 4) ? (ty * 4 + i) : (64 + ty * 4 + (i - 4)));
        #pragma unroll
        for (int h = 0; h < 2; h++) {
            float4 v;
            v.x = silu_f(acc[i][h * 4 + 0]);
            v.y = silu_f(acc[i][h * 4 + 1]);
            v.z = silu_f(acc[i][h * 4 + 2]);
            v.w = silu_f(acc[i][h * 4 + 3]);
            *(float4*)(C + (size_t)r * D + cb + h * 64 + tx * 4) = v;
        }
    }
}

// ---------------- row-wise l2 normalization of K and Q ----------------------
__global__ __launch_bounds__(256) void l2norm_kernel(float* __restrict__ Kp, float* __restrict__ Qp)
{
    float* P = (blockIdx.y == 0) ? Kp : Qp;
    size_t base = (size_t)blockIdx.x * D + threadIdx.x * 4;
    float4 v = *(float4*)(P + base);
    float ss = v.x * v.x + v.y * v.y + v.z * v.z + v.w * v.w;
    #pragma unroll
    for (int o = 16; o > 0; o >>= 1) ss += __shfl_xor_sync(0xffffffffu, ss, o);
    __shared__ float ws[8];
    if ((threadIdx.x & 31) == 0) ws[threadIdx.x >> 5] = ss;
    __syncthreads();
    float tot = 0.f;
    #pragma unroll
    for (int i = 0; i < 8; i++) tot += ws[i];
    float sc = 1.0f / (sqrtf(tot) + 1e-8f);
    v.x *= sc; v.y *= sc; v.z *= sc; v.w *= sc;
    *(float4*)(P + base) = v;
}

// ---------------- per-chunk forgetting gate: alpha[c] ------------------------
// alpha[c] = sigmoid(mean over chunk of (k . Wf)) * 0.1   (deterministic tree reduce)
__global__ __launch_bounds__(256) void alpha_kernel(
    const float* __restrict__ Kp, const float* __restrict__ Wf, float* __restrict__ alpha)
{
    const int c = blockIdx.x, t = threadIdx.x;
    float4 wf = *(const float4*)(Wf + t * 4);
    const float* Kc = Kp + (size_t)c * CSZ * D;
    float s = 0.f;
    #pragma unroll 4
    for (int r = 0; r < CSZ; r++) {
        float4 kv = *(const float4*)(Kc + (size_t)r * D + t * 4);
        s += kv.x * wf.x + kv.y * wf.y + kv.z * wf.z + kv.w * wf.w;
    }
    #pragma unroll
    for (int o = 16; o > 0; o >>= 1) s += __shfl_xor_sync(0xffffffffu, s, o);
    __shared__ float ws[8];
    if ((t & 31) == 0) ws[t >> 5] = s;
    __syncthreads();
    if (t == 0) {
        float tot = 0.f;
        #pragma unroll
        for (int i = 0; i < 8; i++) tot += ws[i];
        float mean = tot * (1.0f / CSZ);
        alpha[c] = 0.1f / (1.0f + __expf(-mean));
    }
}

// ---------------- state update: grad = Kc^T @ err; S, M update --------------
// grid (16,16): 64x64 tile of the 1024x1024 state. err may be V_0 with errscale=-1.
__global__ __launch_bounds__(256) void update_kernel(
    const float* __restrict__ Kp, const float* __restrict__ Err,
    const float* __restrict__ alpha, float* __restrict__ M, float* __restrict__ S,
    int c, float errscale)
{
    __shared__ float Ks[16][64];
    __shared__ float Es[16][64];
    const int t = threadIdx.x;
    const int tx = t & 15, ty = t >> 4;
    const int i0 = blockIdx.y * 64, j0 = blockIdx.x * 64;
    const int lr = t >> 4, lq = t & 15;
    const float* Kc = Kp + (size_t)c * CSZ * D;

    float acc[4][4];
    #pragma unroll
    for (int i = 0; i < 4; i++)
        #pragma unroll
        for (int j = 0; j < 4; j++) acc[i][j] = 0.f;

    for (int r0 = 0; r0 < CSZ; r0 += 16) {
        *(float4*)&Ks[lr][lq * 4] = *(const float4*)(Kc + (size_t)(r0 + lr) * D + i0 + lq * 4);
        *(float4*)&Es[lr][lq * 4] = *(const float4*)(Err + (size_t)(r0 + lr) * D + j0 + lq * 4);
        __syncthreads();
        #pragma unroll
        for (int kk = 0; kk < 16; kk++) {
            float a[4], b[4];
            *(float4*)a = *(float4*)&Ks[kk][ty * 4];
            *(float4*)b = *(float4*)&Es[kk][tx * 4];
            #pragma unroll
            for (int i = 0; i < 4; i++)
                #pragma unroll
                for (int j = 0; j < 4; j++)
                    acc[i][j] = fmaf(a[i], b[j], acc[i][j]);
        }
        __syncthreads();
    }
    const float al = alpha[c];
    const float oma = 1.0f - al;
    const float gsc = errscale * (0.01f / CSZ);   // SURPRISE_LR / CHUNK, signed
    #pragma unroll
    for (int i = 0; i < 4; i++) {
        size_t idx = (size_t)(i0 + ty * 4 + i) * D + j0 + tx * 4;
        float4 s = *(float4*)(S + idx);
        float4 m = *(float4*)(M + idx);
        s.x = 0.9f * s.x - gsc * acc[i][0];
        s.y = 0.9f * s.y - gsc * acc[i][1];
        s.z = 0.9f * s.z - gsc * acc[i][2];
        s.w = 0.9f * s.w - gsc * acc[i][3];
        m.x = oma * m.x + s.x;
        m.y = oma * m.y + s.y;
        m.z = oma * m.z + s.z;
        m.w = oma * m.w + s.w;
        *(float4*)(S + idx) = s;
        *(float4*)(M + idx) = m;
    }
}

// ---------------- combined retrieval + next-chunk error ---------------------
// Row-tiles 0..3: out_c = Q_c @ M. Row-tiles 4..7: err = K_{c+1} @ M - V_{c+1}.
// 32x64x16 tile, 256 threads, 2x4 micro. grid (16, 8) (grid.y=4 on last chunk).
__global__ __launch_bounds__(256) void outerr_kernel(
    const float* __restrict__ Qp, const float* __restrict__ Kp, const float* __restrict__ Vp,
    const float* __restrict__ M, float* __restrict__ out, float* __restrict__ err, int c)
{
    __shared__ float As[16][34];
    __shared__ float Bs[16][64];
    const int t = threadIdx.x;
    const int tx = t & 15, ty = t >> 4;
    const bool isQ = (blockIdx.y < 4);
    const int rtile = isQ ? blockIdx.y : (blockIdx.y - 4);
    const float* A = (isQ ? (Qp + (size_t)c * CSZ * D)
                          : (Kp + (size_t)(c + 1) * CSZ * D)) + (size_t)rtile * 32 * D;
    const int n0 = blockIdx.x * 64;
    const int kr = t >> 4, nq = t & 15;
    const int alr = t >> 2, alk = (t & 3) * 4;

    float acc[2][4];
    #pragma unroll
    for (int i = 0; i < 2; i++)
        #pragma unroll
        for (int j = 0; j < 4; j++) acc[i][j] = 0.f;

    for (int k0 = 0; k0 < D; k0 += 16) {
        if (t < 128) {
            float4 va = *(const float4*)(A + (size_t)alr * D + k0 + alk);
            As[alk + 0][alr] = va.x; As[alk + 1][alr] = va.y;
            As[alk + 2][alr] = va.z; As[alk + 3][alr] = va.w;
        }
        *(float4*)&Bs[kr][nq * 4] = *(const float4*)(M + (size_t)(k0 + kr) * D + n0 + nq * 4);
        __syncthreads();
        #pragma unroll
        for (int kk = 0; kk < 16; kk++) {
            float a0 = As[kk][ty * 2 + 0];
            float a1 = As[kk][ty * 2 + 1];
            float4 b = *(float4*)&Bs[kk][tx * 4];
            acc[0][0] = fmaf(a0, b.x, acc[0][0]);
            acc[0][1] = fmaf(a0, b.y, acc[0][1]);
            acc[0][2] = fmaf(a0, b.z, acc[0][2]);
            acc[0][3] = fmaf(a0, b.w, acc[0][3]);
            acc[1][0] = fmaf(a1, b.x, acc[1][0]);
            acc[1][1] = fmaf(a1, b.y, acc[1][1]);
            acc[1][2] = fmaf(a1, b.z, acc[1][2]);
            acc[1][3] = fmaf(a1, b.w, acc[1][3]);
        }
        __syncthreads();
    }
    const int rloc = rtile * 32 + ty * 2;
    const int col = n0 + tx * 4;
    if (isQ) {
        #pragma unroll
        for (int i = 0; i < 2; i++) {
            float4 v = make_float4(acc[i][0], acc[i][1], acc[i][2], acc[i][3]);
            *(float4*)(out + (size_t)(c * CSZ + rloc + i) * D + col) = v;
        }
    } else {
        #pragma unroll
        for (int i = 0; i < 2; i++) {
            float4 vv = *(const float4*)(Vp + (size_t)((c + 1) * CSZ + rloc + i) * D + col);
            float4 v = make_float4(acc[i][0] - vv.x, acc[i][1] - vv.y,
                                   acc[i][2] - vv.z, acc[i][3] - vv.w);
            *(float4*)(err + (size_t)(rloc + i) * D + col) = v;
        }
    }
}

// ---------------- launcher ----------------------------------------------------
extern "C" void kernel_launch(void* const* d_in, const int* in_sizes, int n_in,
                              void* d_out, int out_size)
{
    const float* x  = (const float*)d_in[0];
    const float* Wk = (const float*)d_in[1];
    const float* Wv = (const float*)d_in[2];
    const float* Wq = (const float*)d_in[3];
    const float* Wf = (const float*)d_in[4];
    float* out = (float*)d_out;

    float *Kp, *Vp, *Qp, *Mp, *Sp, *errp, *alphap;
    cudaGetSymbolAddress((void**)&Kp, g_K);
    cudaGetSymbolAddress((void**)&Vp, g_V);
    cudaGetSymbolAddress((void**)&Qp, g_Q);
    cudaGetSymbolAddress((void**)&Mp, g_M);
    cudaGetSymbolAddress((void**)&Sp, g_S);
    cudaGetSymbolAddress((void**)&errp, g_err);
    cudaGetSymbolAddress((void**)&alphap, g_alpha);

    // Parallel phase: projections (state-independent), then norms + gates.
    dim3 pg(D / 128, SEQ_LEN / 128);
    proj_kernel<<<pg, 256>>>(x, Wk, Kp);
    proj_kernel<<<pg, 256>>>(x, Wv, Vp);
    proj_kernel<<<pg, 256>>>(x, Wq, Qp);
    l2norm_kernel<<<dim3(SEQ_LEN, 2), 256>>>(Kp, Qp);
    alpha_kernel<<<NCH, 256>>>(Kp, Wf, alphap);
    zero_kernel<<<1024, 256>>>(Mp, Sp);

    // Sequential phase: 2 kernels per chunk.
    for (int c = 0; c < NCH; c++) {
        const float* e = (c == 0) ? Vp : errp;          // err_0 = -V_0
        float esc = (c == 0) ? -1.0f : 1.0f;
        update_kernel<<<dim3(16, 16), 256>>>(Kp, e, alphap, Mp, Sp, c, esc);
        dim3 og(16, (c < NCH - 1) ? 8 : 4);
        outerr_kernel<<<og, 256>>>(Qp, Kp, Vp, Mp, out, errp, c);
    }
}

// round 2
// speedup vs baseline: 1.0871x; 1.0871x over previous
#include <cuda_runtime.h>
#include <math.h>

#define SEQ_LEN 16384
#define D       1024
#define CSZ     128
#define NCH     128

// ---------------- scratch (static device globals; no runtime allocs) --------
__device__ float g_K[(size_t)SEQ_LEN * D];
__device__ float g_V[(size_t)SEQ_LEN * D];
__device__ float g_Q[(size_t)SEQ_LEN * D];
__device__ float g_M[D * D];
__device__ float g_S[D * D];
__device__ float g_err[CSZ * D];
__device__ float g_alpha[NCH];

__device__ __forceinline__ float silu_f(float x) { return x / (1.0f + __expf(-x)); }

// ---------------- packed f32x2 helpers (FFMA2: 2 MAC per issue slot) --------
__device__ __forceinline__ unsigned long long splat2(float a) {
    unsigned long long r;
    asm("mov.b64 %0, {%1, %1};" : "=l"(r) : "f"(a));
    return r;
}
__device__ __forceinline__ void fma2(unsigned long long& d, unsigned long long a,
                                     unsigned long long b) {
    asm("fma.rn.f32x2 %0, %1, %2, %0;" : "+l"(d) : "l"(a), "l"(b));
}
__device__ __forceinline__ float2 unpack2(unsigned long long v) {
    float2 r;
    asm("mov.b64 {%0, %1}, %2;" : "=f"(r.x), "=f"(r.y) : "l"(v));
    return r;
}

// ---------------- zero init for M, S ----------------------------------------
__global__ __launch_bounds__(256) void zero_kernel(float* __restrict__ M, float* __restrict__ S)
{
    int idx = blockIdx.x * 256 + threadIdx.x;
    float4 z = make_float4(0.f, 0.f, 0.f, 0.f);
    ((float4*)M)[idx] = z;
    ((float4*)S)[idx] = z;
}

// ---------------- projection GEMM: C = silu(A @ B^T) ------------------------
// 128x128x16 tile, 256 threads, 8x8 micro-tile, FFMA2 inner loop.
__global__ __launch_bounds__(256) void proj_kernel(
    const float* __restrict__ A, const float* __restrict__ B, float* __restrict__ C)
{
    __shared__ float As[16][132];
    __shared__ float Bs[16][132];
    const int t  = threadIdx.x;
    const int tx = t & 15, ty = t >> 4;
    const int lr = t >> 2;
    const int lk = (t & 3) * 4;
    const float* Ab = A + (size_t)blockIdx.y * 128 * D;
    const float* Bb = B + (size_t)blockIdx.x * 128 * D;

    unsigned long long acc[8][4];
    #pragma unroll
    for (int i = 0; i < 8; i++)
        #pragma unroll
        for (int j = 0; j < 4; j++) acc[i][j] = 0ull;

    for (int k0 = 0; k0 < D; k0 += 16) {
        #pragma unroll
        for (int h = 0; h < 2; h++) {
            float4 va = *(const float4*)(Ab + (size_t)(lr + h * 64) * D + k0 + lk);
            As[lk + 0][lr + h * 64] = va.x; As[lk + 1][lr + h * 64] = va.y;
            As[lk + 2][lr + h * 64] = va.z; As[lk + 3][lr + h * 64] = va.w;
            float4 vb = *(const float4*)(Bb + (size_t)(lr + h * 64) * D + k0 + lk);
            Bs[lk + 0][lr + h * 64] = vb.x; Bs[lk + 1][lr + h * 64] = vb.y;
            Bs[lk + 2][lr + h * 64] = vb.z; Bs[lk + 3][lr + h * 64] = vb.w;
        }
        __syncthreads();
        #pragma unroll
        for (int kk = 0; kk < 16; kk++) {
            float a[8];
            *(float4*)&a[0] = *(float4*)&As[kk][ty * 4];
            *(float4*)&a[4] = *(float4*)&As[kk][64 + ty * 4];
            ulonglong2 b0 = *(ulonglong2*)&Bs[kk][tx * 4];
            ulonglong2 b1 = *(ulonglong2*)&Bs[kk][64 + tx * 4];
            #pragma unroll
            for (int i = 0; i < 8; i++) {
                unsigned long long s = splat2(a[i]);
                fma2(acc[i][0], s, b0.x);
                fma2(acc[i][1], s, b0.y);
                fma2(acc[i][2], s, b1.x);
                fma2(acc[i][3], s, b1.y);
            }
        }
        __syncthreads();
    }
    const int rb = blockIdx.y * 128, cb = blockIdx.x * 128;
    #pragma unroll
    for (int i = 0; i < 8; i++) {
        int r = rb + ((i < 4) ? (ty * 4 + i) : (64 + ty * 4 + (i - 4)));
        #pragma unroll
        for (int h = 0; h < 2; h++) {
            float2 p0 = unpack2(acc[i][2 * h + 0]);
            float2 p1 = unpack2(acc[i][2 * h + 1]);
            float4 v;
            v.x = silu_f(p0.x);
            v.y = silu_f(p0.y);
            v.z = silu_f(p1.x);
            v.w = silu_f(p1.y);
            *(float4*)(C + (size_t)r * D + cb + h * 64 + tx * 4) = v;
        }
    }
}

// ---------------- row-wise l2 normalization of K and Q ----------------------
__global__ __launch_bounds__(256) void l2norm_kernel(float* __restrict__ Kp, float* __restrict__ Qp)
{
    float* P = (blockIdx.y == 0) ? Kp : Qp;
    size_t base = (size_t)blockIdx.x * D + threadIdx.x * 4;
    float4 v = *(float4*)(P + base);
    float ss = v.x * v.x + v.y * v.y + v.z * v.z + v.w * v.w;
    #pragma unroll
    for (int o = 16; o > 0; o >>= 1) ss += __shfl_xor_sync(0xffffffffu, ss, o);
    __shared__ float ws[8];
    if ((threadIdx.x & 31) == 0) ws[threadIdx.x >> 5] = ss;
    __syncthreads();
    float tot = 0.f;
    #pragma unroll
    for (int i = 0; i < 8; i++) tot += ws[i];
    float sc = 1.0f / (sqrtf(tot) + 1e-8f);
    v.x *= sc; v.y *= sc; v.z *= sc; v.w *= sc;
    *(float4*)(P + base) = v;
}

// ---------------- per-chunk forgetting gate: alpha[c] ------------------------
__global__ __launch_bounds__(256) void alpha_kernel(
    const float* __restrict__ Kp, const float* __restrict__ Wf, float* __restrict__ alpha)
{
    const int c = blockIdx.x, t = threadIdx.x;
    float4 wf = *(const float4*)(Wf + t * 4);
    const float* Kc = Kp + (size_t)c * CSZ * D;
    float s = 0.f;
    #pragma unroll 4
    for (int r = 0; r < CSZ; r++) {
        float4 kv = *(const float4*)(Kc + (size_t)r * D + t * 4);
        s += kv.x * wf.x + kv.y * wf.y + kv.z * wf.z + kv.w * wf.w;
    }
    #pragma unroll
    for (int o = 16; o > 0; o >>= 1) s += __shfl_xor_sync(0xffffffffu, s, o);
    __shared__ float ws[8];
    if ((t & 31) == 0) ws[t >> 5] = s;
    __syncthreads();
    if (t == 0) {
        float tot = 0.f;
        #pragma unroll
        for (int i = 0; i < 8; i++) tot += ws[i];
        float mean = tot * (1.0f / CSZ);
        alpha[c] = 0.1f / (1.0f + __expf(-mean));
    }
}

// ---------------- state update: grad = Kc^T @ err; S, M update --------------
__global__ __launch_bounds__(256) void update_kernel(
    const float* __restrict__ Kp, const float* __restrict__ Err,
    const float* __restrict__ alpha, float* __restrict__ M, float* __restrict__ S,
    int c, float errscale)
{
    __shared__ float Ks[16][64];
    __shared__ float Es[16][64];
    const int t = threadIdx.x;
    const int tx = t & 15, ty = t >> 4;
    const int i0 = blockIdx.y * 64, j0 = blockIdx.x * 64;
    const int lr = t >> 4, lq = t & 15;
    const float* Kc = Kp + (size_t)c * CSZ * D;

    unsigned long long acc[4][2];
    #pragma unroll
    for (int i = 0; i < 4; i++) { acc[i][0] = 0ull; acc[i][1] = 0ull; }

    for (int r0 = 0; r0 < CSZ; r0 += 16) {
        *(float4*)&Ks[lr][lq * 4] = *(const float4*)(Kc + (size_t)(r0 + lr) * D + i0 + lq * 4);
        *(float4*)&Es[lr][lq * 4] = *(const float4*)(Err + (size_t)(r0 + lr) * D + j0 + lq * 4);
        __syncthreads();
        #pragma unroll
        for (int kk = 0; kk < 16; kk++) {
            float a[4];
            *(float4*)a = *(float4*)&Ks[kk][ty * 4];
            ulonglong2 b = *(ulonglong2*)&Es[kk][tx * 4];
            #pragma unroll
            for (int i = 0; i < 4; i++) {
                unsigned long long s = splat2(a[i]);
                fma2(acc[i][0], s, b.x);
                fma2(acc[i][1], s, b.y);
            }
        }
        __syncthreads();
    }
    const float al = alpha[c];
    const float oma = 1.0f - al;
    const float gsc = errscale * (0.01f / CSZ);
    #pragma unroll
    for (int i = 0; i < 4; i++) {
        size_t idx = (size_t)(i0 + ty * 4 + i) * D + j0 + tx * 4;
        float2 g0 = unpack2(acc[i][0]);
        float2 g1 = unpack2(acc[i][1]);
        float4 s = *(float4*)(S + idx);
        float4 m = *(float4*)(M + idx);
        s.x = 0.9f * s.x - gsc * g0.x;
        s.y = 0.9f * s.y - gsc * g0.y;
        s.z = 0.9f * s.z - gsc * g1.x;
        s.w = 0.9f * s.w - gsc * g1.y;
        m.x = oma * m.x + s.x;
        m.y = oma * m.y + s.y;
        m.z = oma * m.z + s.z;
        m.w = oma * m.w + s.w;
        *(float4*)(S + idx) = s;
        *(float4*)(M + idx) = m;
    }
}

// ---------------- combined retrieval + next-chunk error ---------------------
// Row-tiles 0..3: out_c = Q_c @ M. Row-tiles 4..7: err = K_{c+1} @ M - V_{c+1}.
// 32x64x32 tile, 256 threads, 2x4 micro (FFMA2). grid (16, 8) (y=4 last chunk).
__global__ __launch_bounds__(256) void outerr_kernel(
    const float* __restrict__ Qp, const float* __restrict__ Kp, const float* __restrict__ Vp,
    const float* __restrict__ M, float* __restrict__ out, float* __restrict__ err, int c)
{
    __shared__ float As[32][33];
    __shared__ float Bs[32][64];
    const int t = threadIdx.x;
    const int tx = t & 15, ty = t >> 4;
    const bool isQ = (blockIdx.y < 4);
    const int rtile = isQ ? blockIdx.y : (blockIdx.y - 4);
    const float* A = (isQ ? (Qp + (size_t)c * CSZ * D)
                          : (Kp + (size_t)(c + 1) * CSZ * D)) + (size_t)rtile * 32 * D;
    const int n0 = blockIdx.x * 64;
    const int ar = t >> 3;             // 0..31 (A row)
    const int ak = (t & 7) * 4;        // 0..28 (A k-col)
    const int kr = t >> 4, nq = t & 15;

    unsigned long long acc[2][2];
    acc[0][0] = acc[0][1] = acc[1][0] = acc[1][1] = 0ull;

    for (int k0 = 0; k0 < D; k0 += 32) {
        float4 va = *(const float4*)(A + (size_t)ar * D + k0 + ak);
        As[ak + 0][ar] = va.x; As[ak + 1][ar] = va.y;
        As[ak + 2][ar] = va.z; As[ak + 3][ar] = va.w;
        *(float4*)&Bs[kr][nq * 4]      = *(const float4*)(M + (size_t)(k0 + kr) * D + n0 + nq * 4);
        *(float4*)&Bs[kr + 16][nq * 4] = *(const float4*)(M + (size_t)(k0 + kr + 16) * D + n0 + nq * 4);
        __syncthreads();
        #pragma unroll
        for (int kk = 0; kk < 32; kk++) {
            float a0 = As[kk][ty * 2 + 0];
            float a1 = As[kk][ty * 2 + 1];
            ulonglong2 b = *(ulonglong2*)&Bs[kk][tx * 4];
            unsigned long long s0 = splat2(a0);
            unsigned long long s1 = splat2(a1);
            fma2(acc[0][0], s0, b.x);
            fma2(acc[0][1], s0, b.y);
            fma2(acc[1][0], s1, b.x);
            fma2(acc[1][1], s1, b.y);
        }
        __syncthreads();
    }
    const int rloc = rtile * 32 + ty * 2;
    const int col = n0 + tx * 4;
    if (isQ) {
        #pragma unroll
        for (int i = 0; i < 2; i++) {
            float2 p0 = unpack2(acc[i][0]);
            float2 p1 = unpack2(acc[i][1]);
            float4 v = make_float4(p0.x, p0.y, p1.x, p1.y);
            *(float4*)(out + (size_t)(c * CSZ + rloc + i) * D + col) = v;
        }
    } else {
        #pragma unroll
        for (int i = 0; i < 2; i++) {
            float2 p0 = unpack2(acc[i][0]);
            float2 p1 = unpack2(acc[i][1]);
            float4 vv = *(const float4*)(Vp + (size_t)((c + 1) * CSZ + rloc + i) * D + col);
            float4 v = make_float4(p0.x - vv.x, p0.y - vv.y, p1.x - vv.z, p1.y - vv.w);
            *(float4*)(err + (size_t)(rloc + i) * D + col) = v;
        }
    }
}

// ---------------- launcher ----------------------------------------------------
extern "C" void kernel_launch(void* const* d_in, const int* in_sizes, int n_in,
                              void* d_out, int out_size)
{
    const float* x  = (const float*)d_in[0];
    const float* Wk = (const float*)d_in[1];
    const float* Wv = (const float*)d_in[2];
    const float* Wq = (const float*)d_in[3];
    const float* Wf = (const float*)d_in[4];
    float* out = (float*)d_out;

    float *Kp, *Vp, *Qp, *Mp, *Sp, *errp, *alphap;
    cudaGetSymbolAddress((void**)&Kp, g_K);
    cudaGetSymbolAddress((void**)&Vp, g_V);
    cudaGetSymbolAddress((void**)&Qp, g_Q);
    cudaGetSymbolAddress((void**)&Mp, g_M);
    cudaGetSymbolAddress((void**)&Sp, g_S);
    cudaGetSymbolAddress((void**)&errp, g_err);
    cudaGetSymbolAddress((void**)&alphap, g_alpha);

    // Parallel phase: projections (state-independent), then norms + gates.
    dim3 pg(D / 128, SEQ_LEN / 128);
    proj_kernel<<<pg, 256>>>(x, Wk, Kp);
    proj_kernel<<<pg, 256>>>(x, Wv, Vp);
    proj_kernel<<<pg, 256>>>(x, Wq, Qp);
    l2norm_kernel<<<dim3(SEQ_LEN, 2), 256>>>(Kp, Qp);
    alpha_kernel<<<NCH, 256>>>(Kp, Wf, alphap);
    zero_kernel<<<1024, 256>>>(Mp, Sp);

    // Sequential phase: 2 kernels per chunk.
    for (int c = 0; c < NCH; c++) {
        const float* e = (c == 0) ? Vp : errp;          // err_0 = -V_0
        float esc = (c == 0) ? -1.0f : 1.0f;
        update_kernel<<<dim3(16, 16), 256>>>(Kp, e, alphap, Mp, Sp, c, esc);
        dim3 og(16, (c < NCH - 1) ? 8 : 4);
        outerr_kernel<<<og, 256>>>(Qp, Kp, Vp, Mp, out, errp, c);
    }
}